// round 6
// baseline (speedup 1.0000x reference)
#include <cuda_runtime.h>
#include <cstdint>

#define BB 16
#define CC 80
#define TX 512
#define TY 2048
#define NEGF (-1000000000.0f)

// Output layout (flat concat, fp32):
// z_T [B,TY,C], y_mean_T [B,TY,C], y_ls_T [B,TY,C], attn_T [B,TY,TX], dur [B,TX,1]
#define N_ZT   ((size_t)BB * TY * CC)
#define OFF_Z   ((size_t)0)
#define OFF_M   (N_ZT)
#define OFF_L   (2 * N_ZT)
#define OFF_AT  (3 * N_ZT)
#define OFF_DUR (3 * N_ZT + (size_t)BB * TY * TX)

// ---------------- scratch ----------------
__device__ float g_a   [BB * CC * TX];
__device__ float g_ms  [BB * CC * TX];
__device__ float g_bias[BB * TX];
__device__ float g_logp[(size_t)BB * TY * TX];
__device__ int   g_xs  [BB * TY];
__device__ float g_omT [BB * TX * CC];   // [b][x][c]
__device__ float g_olsT[BB * TX * CC];

// ---------------- f32x2 helpers ----------------
__device__ __forceinline__ unsigned long long pack2(float lo, float hi) {
    unsigned long long r;
    asm("mov.b64 %0, {%1, %2};" : "=l"(r) : "f"(lo), "f"(hi));
    return r;
}
__device__ __forceinline__ float2 unpack2(unsigned long long v) {
    float lo, hi;
    asm("mov.b64 {%0, %1}, %2;" : "=f"(lo), "=f"(hi) : "l"(v));
    return make_float2(lo, hi);
}
__device__ __forceinline__ unsigned long long fma2(unsigned long long a,
                                                   unsigned long long b,
                                                   unsigned long long c) {
    unsigned long long d;
    asm("fma.rn.f32x2 %0, %1, %2, %3;" : "=l"(d) : "l"(a), "l"(b), "l"(c));
    return d;
}
__device__ __forceinline__ unsigned swz(unsigned b) {
    return b ^ ((b >> 3) & 0x70u);
}

// ---------------- kernel 1: prep ----------------
__global__ void __launch_bounds__(128) prep_kernel(const float* __restrict__ om,
                                                   const float* __restrict__ ols) {
    int b = blockIdx.y;
    int x = blockIdx.x * 128 + threadIdx.x;
    float acc = 0.0f;
    for (int c = 0; c < CC; ++c) {
        size_t i = ((size_t)b * CC + c) * TX + x;
        float ls = ols[i];
        float m  = om[i];
        float a  = expf(-2.0f * ls);
        g_a[i]  = a;
        g_ms[i] = m * a;
        acc += -0.9189385332046727f - ls - 0.5f * m * m * a;
    }
    g_bias[b * TX + x] = acc;
}

// ---------------- kernel 2: pre_out (transposes + attn zero-fill) ----------------
#define NFILL 112
__global__ void __launch_bounds__(512) pre_out(const float* __restrict__ z,
                                               const float* __restrict__ om,
                                               const float* __restrict__ ols,
                                               const int* __restrict__ ylen,
                                               float* __restrict__ out) {
    __shared__ float tile[CC * 129];
    int bid = blockIdx.x;
    int tid = threadIdx.x;
    if (bid < 384) {
        int role, idx;
        const float* src;
        int srcN;
        if (bid < 256)      { role = 0; idx = bid;       src = z;   srcN = TY; }
        else if (bid < 320) { role = 1; idx = bid - 256; src = om;  srcN = TX; }
        else                { role = 2; idx = bid - 320; src = ols; srcN = TX; }
        int tilesPerB = (role == 0) ? 16 : 4;
        int b  = idx / tilesPerB;
        int n0 = (idx % tilesPerB) * 128;
        int tyL = ylen[b];
#pragma unroll
        for (int i = 0; i < 5; ++i) {
            int f  = tid + i * 512;
            int c  = f >> 5;
            int s4 = (f & 31) << 2;
            float4 v = *(const float4*)&src[((size_t)b * CC + c) * srcN + n0 + s4];
            int base = c * 129 + s4;
            tile[base]     = v.x;
            tile[base + 1] = v.y;
            tile[base + 2] = v.z;
            tile[base + 3] = v.w;
        }
        __syncthreads();
#pragma unroll
        for (int i = 0; i < 5; ++i) {
            int f  = tid + i * 512;
            int sl = f / 20;
            int c4 = (f % 20) * 4;
            float4 o;
            o.x = tile[(c4 + 0) * 129 + sl];
            o.y = tile[(c4 + 1) * 129 + sl];
            o.z = tile[(c4 + 2) * 129 + sl];
            o.w = tile[(c4 + 3) * 129 + sl];
            int n = n0 + sl;
            if (role == 0) {
                if (n >= tyL) o = make_float4(0.f, 0.f, 0.f, 0.f);
                *(float4*)&out[OFF_Z + ((size_t)b * TY + n) * CC + c4] = o;
            } else {
                float* dst = (role == 1) ? g_omT : g_olsT;
                *(float4*)&dst[((size_t)b * TX + n) * CC + c4] = o;
            }
        }
    } else {
        size_t total = (size_t)BB * TY * TX / 4;
        float4* p = (float4*)&out[OFF_AT];
        float4 zv = make_float4(0.f, 0.f, 0.f, 0.f);
        size_t start = (size_t)(bid - 384) * 512 + tid;
        for (size_t i = start; i < total; i += (size_t)NFILL * 512)
            p[i] = zv;
    }
}

// ---------------- kernel 3: logp GEMM (f32x2, dup-A smem, 128x128 tile) ----------------
#define GEMM_SMEM 49152
__global__ void __launch_bounds__(256, 2) gemm_logp(const float* __restrict__ z,
                                                    const int* __restrict__ xlen,
                                                    const int* __restrict__ ylen) {
    extern __shared__ __align__(16) unsigned char gsm[];
    unsigned char* smA  = gsm;
    unsigned char* smM  = gsm + 16384;
    unsigned char* smZ1 = gsm + 32768;
    unsigned char* smZ2 = gsm + 40960;

    int b  = blockIdx.z;
    int x0 = blockIdx.x * 128;
    int y0 = blockIdx.y * 128;
    int tid = threadIdx.x;
    int txi = tid & 15;
    int tyi = tid >> 4;
    int xl = txi * 8;
    int yl = tyi * 8;

    unsigned aoff[4];
#pragma unroll
    for (int g = 0; g < 4; ++g) aoff[g] = swz((unsigned)(txi * 64 + g * 16));
    unsigned zoff = (unsigned)(tyi * 32);

    unsigned long long acc[8][4];   // [x_local][y_pair]
#pragma unroll
    for (int i = 0; i < 8; ++i)
#pragma unroll
        for (int j = 0; j < 4; ++j) acc[i][j] = 0ULL;

    for (int kc = 0; kc < CC; kc += 16) {
        __syncthreads();
#pragma unroll
        for (int i = 0; i < 2; ++i) {
            int f  = tid + i * 256;
            int r  = f >> 5;
            int c4 = (f & 31) << 2;
            size_t gi = ((size_t)b * CC + kc + r) * TX + x0 + c4;
            float4 av = *(const float4*)&g_a[gi];
            float4 mv = *(const float4*)&g_ms[gi];
            unsigned sb0 = swz((unsigned)(c4 * 8));
            unsigned sb1 = swz((unsigned)(c4 * 8 + 16));
            *(ulonglong2*)(smA + r * 1024 + sb0) = make_ulonglong2(pack2(av.x, av.x), pack2(av.y, av.y));
            *(ulonglong2*)(smA + r * 1024 + sb1) = make_ulonglong2(pack2(av.z, av.z), pack2(av.w, av.w));
            *(ulonglong2*)(smM + r * 1024 + sb0) = make_ulonglong2(pack2(mv.x, mv.x), pack2(mv.y, mv.y));
            *(ulonglong2*)(smM + r * 1024 + sb1) = make_ulonglong2(pack2(mv.z, mv.z), pack2(mv.w, mv.w));
        }
#pragma unroll
        for (int i = 0; i < 2; ++i) {
            int f  = tid + i * 256;
            int r  = f >> 5;
            int c4 = (f & 31) << 2;
            size_t gi = ((size_t)b * CC + kc + r) * TY + y0 + c4;
            float4 zv = *(const float4*)&z[gi];
            ulonglong2* p1 = (ulonglong2*)(smZ1 + r * 512 + (f & 31) * 16);
            ulonglong2* p2 = (ulonglong2*)(smZ2 + r * 512 + (f & 31) * 16);
            *p1 = make_ulonglong2(pack2(zv.x, zv.y), pack2(zv.z, zv.w));
            *p2 = make_ulonglong2(pack2(-0.5f * zv.x * zv.x, -0.5f * zv.y * zv.y),
                                  pack2(-0.5f * zv.z * zv.z, -0.5f * zv.w * zv.w));
        }
        __syncthreads();
#pragma unroll
        for (int k = 0; k < 16; ++k) {
            const unsigned char* rowA = smA + k * 1024;
            const unsigned char* rowM = smM + k * 1024;
            ulonglong2 z1a = *(const ulonglong2*)(smZ1 + k * 512 + zoff);
            ulonglong2 z1b = *(const ulonglong2*)(smZ1 + k * 512 + zoff + 16);
            ulonglong2 z2a = *(const ulonglong2*)(smZ2 + k * 512 + zoff);
            ulonglong2 z2b = *(const ulonglong2*)(smZ2 + k * 512 + zoff + 16);
            unsigned long long z1p[4] = {z1a.x, z1a.y, z1b.x, z1b.y};
            unsigned long long z2p[4] = {z2a.x, z2a.y, z2b.x, z2b.y};
#pragma unroll
            for (int g = 0; g < 4; ++g) {
                ulonglong2 a2 = *(const ulonglong2*)(rowA + aoff[g]);
                ulonglong2 m2 = *(const ulonglong2*)(rowM + aoff[g]);
#pragma unroll
                for (int yp = 0; yp < 4; ++yp) {
                    acc[2 * g][yp]     = fma2(a2.x, z2p[yp], acc[2 * g][yp]);
                    acc[2 * g][yp]     = fma2(m2.x, z1p[yp], acc[2 * g][yp]);
                    acc[2 * g + 1][yp] = fma2(a2.y, z2p[yp], acc[2 * g + 1][yp]);
                    acc[2 * g + 1][yp] = fma2(m2.y, z1p[yp], acc[2 * g + 1][yp]);
                }
            }
        }
    }

    int txL = xlen[b], tyL = ylen[b];
    float bv[8];
    *(float4*)&bv[0] = *(const float4*)&g_bias[b * TX + x0 + xl];
    *(float4*)&bv[4] = *(const float4*)&g_bias[b * TX + x0 + xl + 4];
#pragma unroll
    for (int yy = 0; yy < 8; ++yy) {
        int y = y0 + yl + yy;
        bool yok = (y < tyL);
        int yp = yy >> 1;
        bool hi = (yy & 1);
        float o[8];
#pragma unroll
        for (int j = 0; j < 8; ++j) {
            float2 u = unpack2(acc[j][yp]);
            float v = hi ? u.y : u.x;
            int x = x0 + xl + j;
            o[j] = (yok && x < txL) ? (bv[j] + v) : 0.0f;
        }
        size_t base = ((size_t)b * TY + y) * TX + x0 + xl;
        *(float4*)&g_logp[base]     = make_float4(o[0], o[1], o[2], o[3]);
        *(float4*)&g_logp[base + 4] = make_float4(o[4], o[5], o[6], o[7]);
    }
}

// ---------------- kernel 4: DP forward (4-warp systolic) + backtrack ----------------
// smem: sd[TY*16] u32 (128KB) | bnd[4][TY] float (32KB) | sxs[TY] int (8KB)
#define DPW 4
#define CHUNK 16
#define FWD_SMEM (TY * 16 * 4 + DPW * TY * 4 + TY * 4)

__global__ void __launch_bounds__(128) fwd_kernel(const int* __restrict__ xlen,
                                                  const int* __restrict__ ylen,
                                                  float* __restrict__ out) {
    extern __shared__ unsigned char fsm[];
    unsigned* sd = (unsigned*)fsm;                               // [TY][16]
    float* bnd = (float*)(fsm + (size_t)TY * 16 * 4);            // [DPW][TY]
    int* sxs = (int*)(fsm + (size_t)TY * 16 * 4 + DPW * TY * 4); // [TY]

    int b = blockIdx.x;
    int tid = threadIdx.x;
    int w = tid >> 5, lane = tid & 31;
    const float4* lp4 = (const float4*)&g_logp[(size_t)b * TY * TX];
    int lidx = w * 32 + lane;               // float4 index within a column
    int gx0 = lidx * 4;                     // global x of element 0
    float* mybnd = bnd + w * TY;
    const float* pbnd = bnd + (w - 1) * TY;

    float4 buf[8];
#pragma unroll
    for (int q = 0; q < 8; ++q) buf[q] = lp4[q * 128 + lidx];

    float r0 = NEGF, r1 = NEGF, r2 = NEGF, r3 = NEGF;

    for (int c = 0; c < TY / CHUNK; ++c) {
        if (w > 0) asm volatile("bar.sync %0, 64;" :: "r"(8 + w));
#pragma unroll 4
        for (int j = 0; j < CHUNK; ++j) {
            int y = c * CHUNK + j;
            float4 cc = buf[y & 7];
            if (y + 8 < TY) buf[y & 7] = lp4[(size_t)(y + 8) * 128 + lidx];
            if (y == 0) {
                r0 = (gx0 == 0) ? cc.x : NEGF;
                r1 = r2 = r3 = NEGF;
            } else {
                float left = __shfl_up_sync(0xffffffffu, r3, 1);
                if (lane == 0) left = (w == 0) ? NEGF : pbnd[y - 1];
                bool c1 = r0 > r1, c2 = r1 > r2, c3 = r2 > r3;
                r3 = cc.w + fmaxf(r3, r2);
                r2 = cc.z + fmaxf(r2, r1);
                r1 = cc.y + fmaxf(r1, r0);
                bool c0 = left > r0;
                r0 = cc.x + fmaxf(r0, left);
                unsigned B0 = __ballot_sync(0xffffffffu, c0);
                unsigned B1 = __ballot_sync(0xffffffffu, c1);
                unsigned B2 = __ballot_sync(0xffffffffu, c2);
                unsigned B3 = __ballot_sync(0xffffffffu, c3);
                if (lane == 0)
                    *(uint4*)&sd[(y - 1) * 16 + w * 4] = make_uint4(B0, B1, B2, B3);
            }
            if (lane == 31) mybnd[y] = r3;
        }
        if (w < DPW - 1) asm volatile("bar.sync %0, 64;" :: "r"(9 + w));
    }
    __syncthreads();

    int txL = xlen[b], tyL = ylen[b];
    if (tid == 0) {
        int idx = txL - 1;
        for (int y = tyL - 1; y >= 0; --y) {
            sxs[y] = idx;
            int mv = 0;
            if (idx > 0) {
                if (idx == y) {
                    mv = 1;
                } else {
                    unsigned word = sd[(y - 1) * 16 + ((idx >> 7) << 2) + (idx & 3)];
                    mv = (word >> ((idx >> 2) & 31)) & 1;
                }
            }
            idx -= mv;
        }
    }
    __syncthreads();
    // publish xs
    for (int y = tid; y < tyL; y += 128) g_xs[b * TY + y] = sxs[y];
    for (int y = tyL + tid; y < TY; y += 128) g_xs[b * TY + y] = -1;
    // durations via binary search over monotone sxs[0..tyL)
#pragma unroll
    for (int h = 0; h < 4; ++h) {
        int x = h * 128 + tid;
        float dv = 0.0f;
        if (x < txL) {
            int lo = 0, hi = tyL;
            while (lo < hi) { int mid = (lo + hi) >> 1; if (sxs[mid] < x) lo = mid + 1; else hi = mid; }
            int start = lo;
            hi = tyL;
            while (lo < hi) { int mid = (lo + hi) >> 1; if (sxs[mid] < x + 1) lo = mid + 1; else hi = mid; }
            dv = log1pf((float)(lo - start));
        }
        out[OFF_DUR + b * TX + x] = dv;
    }
}

// ---------------- kernel 5: gathers + attn ones ----------------
__global__ void __launch_bounds__(256) gather_kernel(float* __restrict__ out) {
    int t = blockIdx.x * 256 + threadIdx.x;
    if (t >= BB * TY * 20) return;
    int bs = t / 20;
    int c4 = (t % 20) * 4;
    int b  = bs >> 11;
    int xs = g_xs[bs];
    float4 m = make_float4(0.f, 0.f, 0.f, 0.f), l = m;
    if (xs >= 0) {
        size_t rb = ((size_t)b * TX + xs) * CC + c4;
        m = *(const float4*)&g_omT[rb];
        l = *(const float4*)&g_olsT[rb];
        if (c4 == 0) out[OFF_AT + (size_t)bs * TX + xs] = 1.0f;
    }
    *(float4*)&out[OFF_M + (size_t)bs * CC + c4] = m;
    *(float4*)&out[OFF_L + (size_t)bs * CC + c4] = l;
}

// ---------------- launch ----------------
extern "C" void kernel_launch(void* const* d_in, const int* in_sizes, int n_in,
                              void* d_out, int out_size) {
    const float* om   = (const float*)d_in[0];
    const float* ols  = (const float*)d_in[1];
    const float* z    = (const float*)d_in[2];
    const int*   xlen = (const int*)d_in[3];
    const int*   ylen = (const int*)d_in[4];
    float* out = (float*)d_out;

    static bool attr_set = false;
    if (!attr_set) {
        cudaFuncSetAttribute(fwd_kernel, cudaFuncAttributeMaxDynamicSharedMemorySize, FWD_SMEM);
        cudaFuncSetAttribute(gemm_logp, cudaFuncAttributeMaxDynamicSharedMemorySize, GEMM_SMEM);
        attr_set = true;
    }

    prep_kernel<<<dim3(TX / 128, BB), 128>>>(om, ols);
    pre_out<<<496, 512>>>(z, om, ols, ylen, out);
    gemm_logp<<<dim3(TX / 128, TY / 128, BB), 256, GEMM_SMEM>>>(z, xlen, ylen);
    fwd_kernel<<<BB, DPW * 32, FWD_SMEM>>>(xlen, ylen, out);
    gather_kernel<<<(BB * TY * 20 + 255) / 256, 256>>>(out);
}

// round 7
// speedup vs baseline: 1.8369x; 1.8369x over previous
#include <cuda_runtime.h>
#include <cstdint>

#define BB 16
#define CC 80
#define TX 512
#define TY 2048
#define NEGF (-1000000000.0f)

// Output layout (flat concat, fp32):
// z_T [B,TY,C], y_mean_T [B,TY,C], y_ls_T [B,TY,C], attn_T [B,TY,TX], dur [B,TX,1]
#define N_ZT   ((size_t)BB * TY * CC)
#define OFF_Z   ((size_t)0)
#define OFF_M   (N_ZT)
#define OFF_L   (2 * N_ZT)
#define OFF_AT  (3 * N_ZT)
#define OFF_DUR (3 * N_ZT + (size_t)BB * TY * TX)

// ---------------- scratch ----------------
__device__ float g_a   [BB * CC * TX];
__device__ float g_ms  [BB * CC * TX];
__device__ float g_bias[BB * TX];
__device__ float g_logp[(size_t)BB * TY * TX];
__device__ int   g_xs  [BB * TY];
__device__ float g_omT [BB * TX * CC];   // [b][x][c]
__device__ float g_olsT[BB * TX * CC];

// ---------------- f32x2 helpers ----------------
__device__ __forceinline__ unsigned long long pack2(float lo, float hi) {
    unsigned long long r;
    asm("mov.b64 %0, {%1, %2};" : "=l"(r) : "f"(lo), "f"(hi));
    return r;
}
__device__ __forceinline__ float2 unpack2(unsigned long long v) {
    float lo, hi;
    asm("mov.b64 {%0, %1}, %2;" : "=f"(lo), "=f"(hi) : "l"(v));
    return make_float2(lo, hi);
}
__device__ __forceinline__ unsigned long long fma2(unsigned long long a,
                                                   unsigned long long b,
                                                   unsigned long long c) {
    unsigned long long d;
    asm("fma.rn.f32x2 %0, %1, %2, %3;" : "=l"(d) : "l"(a), "l"(b), "l"(c));
    return d;
}
__device__ __forceinline__ unsigned swz(unsigned b) {
    return b ^ ((b >> 3) & 0x70u);
}

// ---------------- kernel 1: prep ----------------
__global__ void __launch_bounds__(128) prep_kernel(const float* __restrict__ om,
                                                   const float* __restrict__ ols) {
    int b = blockIdx.y;
    int x = blockIdx.x * 128 + threadIdx.x;
    float acc = 0.0f;
    for (int c = 0; c < CC; ++c) {
        size_t i = ((size_t)b * CC + c) * TX + x;
        float ls = ols[i];
        float m  = om[i];
        float a  = expf(-2.0f * ls);
        g_a[i]  = a;
        g_ms[i] = m * a;
        acc += -0.9189385332046727f - ls - 0.5f * m * m * a;
    }
    g_bias[b * TX + x] = acc;
}

// ---------------- kernel 2: pre_out (transposes + attn zero-fill) ----------------
#define NFILL 112
__global__ void __launch_bounds__(512) pre_out(const float* __restrict__ z,
                                               const float* __restrict__ om,
                                               const float* __restrict__ ols,
                                               const int* __restrict__ ylen,
                                               float* __restrict__ out) {
    __shared__ float tile[CC * 129];
    int bid = blockIdx.x;
    int tid = threadIdx.x;
    if (bid < 384) {
        int role, idx;
        const float* src;
        int srcN;
        if (bid < 256)      { role = 0; idx = bid;       src = z;   srcN = TY; }
        else if (bid < 320) { role = 1; idx = bid - 256; src = om;  srcN = TX; }
        else                { role = 2; idx = bid - 320; src = ols; srcN = TX; }
        int tilesPerB = (role == 0) ? 16 : 4;
        int b  = idx / tilesPerB;
        int n0 = (idx % tilesPerB) * 128;
        int tyL = ylen[b];
#pragma unroll
        for (int i = 0; i < 5; ++i) {
            int f  = tid + i * 512;
            int c  = f >> 5;
            int s4 = (f & 31) << 2;
            float4 v = *(const float4*)&src[((size_t)b * CC + c) * srcN + n0 + s4];
            int base = c * 129 + s4;
            tile[base]     = v.x;
            tile[base + 1] = v.y;
            tile[base + 2] = v.z;
            tile[base + 3] = v.w;
        }
        __syncthreads();
#pragma unroll
        for (int i = 0; i < 5; ++i) {
            int f  = tid + i * 512;
            int sl = f / 20;
            int c4 = (f % 20) * 4;
            float4 o;
            o.x = tile[(c4 + 0) * 129 + sl];
            o.y = tile[(c4 + 1) * 129 + sl];
            o.z = tile[(c4 + 2) * 129 + sl];
            o.w = tile[(c4 + 3) * 129 + sl];
            int n = n0 + sl;
            if (role == 0) {
                if (n >= tyL) o = make_float4(0.f, 0.f, 0.f, 0.f);
                *(float4*)&out[OFF_Z + ((size_t)b * TY + n) * CC + c4] = o;
            } else {
                float* dst = (role == 1) ? g_omT : g_olsT;
                *(float4*)&dst[((size_t)b * TX + n) * CC + c4] = o;
            }
        }
    } else {
        size_t total = (size_t)BB * TY * TX / 4;
        float4* p = (float4*)&out[OFF_AT];
        float4 zv = make_float4(0.f, 0.f, 0.f, 0.f);
        size_t start = (size_t)(bid - 384) * 512 + tid;
        for (size_t i = start; i < total; i += (size_t)NFILL * 512)
            p[i] = zv;
    }
}

// ---------------- kernel 3: logp GEMM (f32x2, dup-A smem, 128x128 tile) ----------------
#define GEMM_SMEM 49152
__global__ void __launch_bounds__(256, 2) gemm_logp(const float* __restrict__ z,
                                                    const int* __restrict__ xlen,
                                                    const int* __restrict__ ylen) {
    extern __shared__ __align__(16) unsigned char gsm[];
    unsigned char* smA  = gsm;
    unsigned char* smM  = gsm + 16384;
    unsigned char* smZ1 = gsm + 32768;
    unsigned char* smZ2 = gsm + 40960;

    int b  = blockIdx.z;
    int x0 = blockIdx.x * 128;
    int y0 = blockIdx.y * 128;
    int tid = threadIdx.x;
    int txi = tid & 15;
    int tyi = tid >> 4;
    int xl = txi * 8;
    int yl = tyi * 8;

    unsigned aoff[4];
#pragma unroll
    for (int g = 0; g < 4; ++g) aoff[g] = swz((unsigned)(txi * 64 + g * 16));
    unsigned zoff = (unsigned)(tyi * 32);

    unsigned long long acc[8][4];   // [x_local][y_pair]
#pragma unroll
    for (int i = 0; i < 8; ++i)
#pragma unroll
        for (int j = 0; j < 4; ++j) acc[i][j] = 0ULL;

    for (int kc = 0; kc < CC; kc += 16) {
        __syncthreads();
#pragma unroll
        for (int i = 0; i < 2; ++i) {
            int f  = tid + i * 256;
            int r  = f >> 5;
            int c4 = (f & 31) << 2;
            size_t gi = ((size_t)b * CC + kc + r) * TX + x0 + c4;
            float4 av = *(const float4*)&g_a[gi];
            float4 mv = *(const float4*)&g_ms[gi];
            unsigned sb0 = swz((unsigned)(c4 * 8));
            unsigned sb1 = swz((unsigned)(c4 * 8 + 16));
            *(ulonglong2*)(smA + r * 1024 + sb0) = make_ulonglong2(pack2(av.x, av.x), pack2(av.y, av.y));
            *(ulonglong2*)(smA + r * 1024 + sb1) = make_ulonglong2(pack2(av.z, av.z), pack2(av.w, av.w));
            *(ulonglong2*)(smM + r * 1024 + sb0) = make_ulonglong2(pack2(mv.x, mv.x), pack2(mv.y, mv.y));
            *(ulonglong2*)(smM + r * 1024 + sb1) = make_ulonglong2(pack2(mv.z, mv.z), pack2(mv.w, mv.w));
        }
#pragma unroll
        for (int i = 0; i < 2; ++i) {
            int f  = tid + i * 256;
            int r  = f >> 5;
            int c4 = (f & 31) << 2;
            size_t gi = ((size_t)b * CC + kc + r) * TY + y0 + c4;
            float4 zv = *(const float4*)&z[gi];
            ulonglong2* p1 = (ulonglong2*)(smZ1 + r * 512 + (f & 31) * 16);
            ulonglong2* p2 = (ulonglong2*)(smZ2 + r * 512 + (f & 31) * 16);
            *p1 = make_ulonglong2(pack2(zv.x, zv.y), pack2(zv.z, zv.w));
            *p2 = make_ulonglong2(pack2(-0.5f * zv.x * zv.x, -0.5f * zv.y * zv.y),
                                  pack2(-0.5f * zv.z * zv.z, -0.5f * zv.w * zv.w));
        }
        __syncthreads();
#pragma unroll
        for (int k = 0; k < 16; ++k) {
            const unsigned char* rowA = smA + k * 1024;
            const unsigned char* rowM = smM + k * 1024;
            ulonglong2 z1a = *(const ulonglong2*)(smZ1 + k * 512 + zoff);
            ulonglong2 z1b = *(const ulonglong2*)(smZ1 + k * 512 + zoff + 16);
            ulonglong2 z2a = *(const ulonglong2*)(smZ2 + k * 512 + zoff);
            ulonglong2 z2b = *(const ulonglong2*)(smZ2 + k * 512 + zoff + 16);
            unsigned long long z1p[4] = {z1a.x, z1a.y, z1b.x, z1b.y};
            unsigned long long z2p[4] = {z2a.x, z2a.y, z2b.x, z2b.y};
#pragma unroll
            for (int g = 0; g < 4; ++g) {
                ulonglong2 a2 = *(const ulonglong2*)(rowA + aoff[g]);
                ulonglong2 m2 = *(const ulonglong2*)(rowM + aoff[g]);
#pragma unroll
                for (int yp = 0; yp < 4; ++yp) {
                    acc[2 * g][yp]     = fma2(a2.x, z2p[yp], acc[2 * g][yp]);
                    acc[2 * g][yp]     = fma2(m2.x, z1p[yp], acc[2 * g][yp]);
                    acc[2 * g + 1][yp] = fma2(a2.y, z2p[yp], acc[2 * g + 1][yp]);
                    acc[2 * g + 1][yp] = fma2(m2.y, z1p[yp], acc[2 * g + 1][yp]);
                }
            }
        }
    }

    int txL = xlen[b], tyL = ylen[b];
    float bv[8];
    *(float4*)&bv[0] = *(const float4*)&g_bias[b * TX + x0 + xl];
    *(float4*)&bv[4] = *(const float4*)&g_bias[b * TX + x0 + xl + 4];
#pragma unroll
    for (int yy = 0; yy < 8; ++yy) {
        int y = y0 + yl + yy;
        bool yok = (y < tyL);
        int yp = yy >> 1;
        bool hi = (yy & 1);
        float o[8];
#pragma unroll
        for (int j = 0; j < 8; ++j) {
            float2 u = unpack2(acc[j][yp]);
            float v = hi ? u.y : u.x;
            int x = x0 + xl + j;
            o[j] = (yok && x < txL) ? (bv[j] + v) : 0.0f;
        }
        size_t base = ((size_t)b * TY + y) * TX + x0 + xl;
        *(float4*)&g_logp[base]     = make_float4(o[0], o[1], o[2], o[3]);
        *(float4*)&g_logp[base + 4] = make_float4(o[4], o[5], o[6], o[7]);
    }
}

// ---------------- kernel 4: DP forward (4-warp systolic, fully unrolled chunks) ----------------
// smem: sd[TY*16] u32 (128KB) | bnd[4][TY] float (32KB) | sxs[TY] int (8KB)
#define DPW 4
#define CHUNK 16
#define FWD_SMEM (TY * 16 * 4 + DPW * TY * 4 + TY * 4)

__global__ void __launch_bounds__(128) fwd_kernel(const int* __restrict__ xlen,
                                                  const int* __restrict__ ylen,
                                                  float* __restrict__ out) {
    extern __shared__ unsigned char fsm[];
    unsigned* sd = (unsigned*)fsm;                               // [TY][16]
    float* bnd = (float*)(fsm + (size_t)TY * 16 * 4);            // [DPW][TY]
    int* sxs = (int*)(fsm + (size_t)TY * 16 * 4 + DPW * TY * 4); // [TY]

    int b = blockIdx.x;
    int tid = threadIdx.x;
    int w = tid >> 5, lane = tid & 31;
    const float4* lp4 = (const float4*)&g_logp[(size_t)b * TY * TX];
    int lidx = w * 32 + lane;               // float4 index within a column
    int gx0 = lidx * 4;                     // global x of element 0
    float* mybnd = bnd + w * TY;
    const float* pbnd = bnd + (w - 1) * TY;

    // register ring, CHUNK deep: prefetch one full chunk ahead
    float4 buf[CHUNK];
#pragma unroll
    for (int q = 0; q < CHUNK; ++q) buf[q] = lp4[q * 128 + lidx];

    float r0 = NEGF, r1 = NEGF, r2 = NEGF, r3 = NEGF;

    for (int c = 0; c < TY / CHUNK; ++c) {
        if (w > 0) asm volatile("bar.sync %0, 64;" :: "r"(8 + w));
#pragma unroll
        for (int j = 0; j < CHUNK; ++j) {
            int y = c * CHUNK + j;
            float4 cc = buf[j];
            if (c + 1 < TY / CHUNK) buf[j] = lp4[(size_t)(y + CHUNK) * 128 + lidx];
            if (y == 0) {
                r0 = (gx0 == 0) ? cc.x : NEGF;
                r1 = r2 = r3 = NEGF;
                if (lane == 31) mybnd[0] = r3;
            } else {
                float left = __shfl_up_sync(0xffffffffu, r3, 1);
                if (lane == 0) left = (w == 0) ? NEGF : pbnd[y - 1];
                bool c1 = r0 > r1, c2 = r1 > r2, c3 = r2 > r3;
                r3 = cc.w + fmaxf(r3, r2);
                r2 = cc.z + fmaxf(r2, r1);
                r1 = cc.y + fmaxf(r1, r0);
                bool c0 = left > r0;
                r0 = cc.x + fmaxf(r0, left);
                unsigned B0 = __ballot_sync(0xffffffffu, c0);
                unsigned B1 = __ballot_sync(0xffffffffu, c1);
                unsigned B2 = __ballot_sync(0xffffffffu, c2);
                unsigned B3 = __ballot_sync(0xffffffffu, c3);
                if (lane == 0)
                    *(uint4*)&sd[(y - 1) * 16 + w * 4] = make_uint4(B0, B1, B2, B3);
                if (lane == 31) mybnd[y] = r3;
            }
        }
        if (w < DPW - 1) asm volatile("bar.sync %0, 64;" :: "r"(9 + w));
    }
    __syncthreads();

    int txL = xlen[b], tyL = ylen[b];
    if (tid == 0) {
        int idx = txL - 1;
        for (int y = tyL - 1; y >= 0; --y) {
            sxs[y] = idx;
            int mv = 0;
            if (idx > 0) {
                if (idx == y) {
                    mv = 1;
                } else {
                    unsigned word = sd[(y - 1) * 16 + ((idx >> 7) << 2) + (idx & 3)];
                    mv = (word >> ((idx >> 2) & 31)) & 1;
                }
            }
            idx -= mv;
        }
    }
    __syncthreads();
    // publish xs
    for (int y = tid; y < tyL; y += 128) g_xs[b * TY + y] = sxs[y];
    for (int y = tyL + tid; y < TY; y += 128) g_xs[b * TY + y] = -1;
    // durations via binary search over monotone sxs[0..tyL)
#pragma unroll
    for (int h = 0; h < 4; ++h) {
        int x = h * 128 + tid;
        float dv = 0.0f;
        if (x < txL) {
            int lo = 0, hi = tyL;
            while (lo < hi) { int mid = (lo + hi) >> 1; if (sxs[mid] < x) lo = mid + 1; else hi = mid; }
            int start = lo;
            hi = tyL;
            while (lo < hi) { int mid = (lo + hi) >> 1; if (sxs[mid] < x + 1) lo = mid + 1; else hi = mid; }
            dv = log1pf((float)(lo - start));
        }
        out[OFF_DUR + b * TX + x] = dv;
    }
}

// ---------------- kernel 5: gathers + attn ones ----------------
__global__ void __launch_bounds__(256) gather_kernel(float* __restrict__ out) {
    int t = blockIdx.x * 256 + threadIdx.x;
    if (t >= BB * TY * 20) return;
    int bs = t / 20;
    int c4 = (t % 20) * 4;
    int b  = bs >> 11;
    int xs = g_xs[bs];
    float4 m = make_float4(0.f, 0.f, 0.f, 0.f), l = m;
    if (xs >= 0) {
        size_t rb = ((size_t)b * TX + xs) * CC + c4;
        m = *(const float4*)&g_omT[rb];
        l = *(const float4*)&g_olsT[rb];
        if (c4 == 0) out[OFF_AT + (size_t)bs * TX + xs] = 1.0f;
    }
    *(float4*)&out[OFF_M + (size_t)bs * CC + c4] = m;
    *(float4*)&out[OFF_L + (size_t)bs * CC + c4] = l;
}

// ---------------- launch ----------------
extern "C" void kernel_launch(void* const* d_in, const int* in_sizes, int n_in,
                              void* d_out, int out_size) {
    const float* om   = (const float*)d_in[0];
    const float* ols  = (const float*)d_in[1];
    const float* z    = (const float*)d_in[2];
    const int*   xlen = (const int*)d_in[3];
    const int*   ylen = (const int*)d_in[4];
    float* out = (float*)d_out;

    static bool attr_set = false;
    if (!attr_set) {
        cudaFuncSetAttribute(fwd_kernel, cudaFuncAttributeMaxDynamicSharedMemorySize, FWD_SMEM);
        cudaFuncSetAttribute(gemm_logp, cudaFuncAttributeMaxDynamicSharedMemorySize, GEMM_SMEM);
        attr_set = true;
    }

    prep_kernel<<<dim3(TX / 128, BB), 128>>>(om, ols);
    pre_out<<<496, 512>>>(z, om, ols, ylen, out);
    gemm_logp<<<dim3(TX / 128, TY / 128, BB), 256, GEMM_SMEM>>>(z, xlen, ylen);
    fwd_kernel<<<BB, DPW * 32, FWD_SMEM>>>(xlen, ylen, out);
    gather_kernel<<<(BB * TY * 20 + 255) / 256, 256>>>(out);
}

// round 8
// speedup vs baseline: 1.9619x; 1.0680x over previous
#include <cuda_runtime.h>
#include <cstdint>

#define BB 16
#define CC 80
#define TX 512
#define TY 2048
#define NEGF (-1000000000.0f)

// Output layout (flat concat, fp32):
// z_T [B,TY,C], y_mean_T [B,TY,C], y_ls_T [B,TY,C], attn_T [B,TY,TX], dur [B,TX,1]
#define N_ZT   ((size_t)BB * TY * CC)
#define OFF_Z   ((size_t)0)
#define OFF_M   (N_ZT)
#define OFF_L   (2 * N_ZT)
#define OFF_AT  (3 * N_ZT)
#define OFF_DUR (3 * N_ZT + (size_t)BB * TY * TX)

// ---------------- scratch ----------------
__device__ float g_a   [BB * CC * TX];
__device__ float g_ms  [BB * CC * TX];
__device__ float g_bias[BB * TX];
__device__ float g_logp[(size_t)BB * TY * TX];
__device__ int   g_xs  [BB * TY];
__device__ float g_omT [BB * TX * CC];   // [b][x][c]
__device__ float g_olsT[BB * TX * CC];

// ---------------- f32x2 helpers ----------------
__device__ __forceinline__ unsigned long long pack2(float lo, float hi) {
    unsigned long long r;
    asm("mov.b64 %0, {%1, %2};" : "=l"(r) : "f"(lo), "f"(hi));
    return r;
}
__device__ __forceinline__ float2 unpack2(unsigned long long v) {
    float lo, hi;
    asm("mov.b64 {%0, %1}, %2;" : "=f"(lo), "=f"(hi) : "l"(v));
    return make_float2(lo, hi);
}
__device__ __forceinline__ unsigned long long fma2(unsigned long long a,
                                                   unsigned long long b,
                                                   unsigned long long c) {
    unsigned long long d;
    asm("fma.rn.f32x2 %0, %1, %2, %3;" : "=l"(d) : "l"(a), "l"(b), "l"(c));
    return d;
}
__device__ __forceinline__ unsigned swz(unsigned b) {
    return b ^ ((b >> 3) & 0x70u);
}
__device__ __forceinline__ void cp16(unsigned smem_addr, const void* gptr) {
    asm volatile("cp.async.ca.shared.global [%0], [%1], 16;\n"
                 :: "r"(smem_addr), "l"(gptr));
}
#define CP_COMMIT() asm volatile("cp.async.commit_group;\n" ::: "memory")
#define CP_WAIT(n)  asm volatile("cp.async.wait_group %0;\n" :: "n"(n) : "memory")

// ---------------- kernel 1: prep ----------------
__global__ void __launch_bounds__(128) prep_kernel(const float* __restrict__ om,
                                                   const float* __restrict__ ols) {
    int b = blockIdx.y;
    int x = blockIdx.x * 128 + threadIdx.x;
    float acc = 0.0f;
    for (int c = 0; c < CC; ++c) {
        size_t i = ((size_t)b * CC + c) * TX + x;
        float ls = ols[i];
        float m  = om[i];
        float a  = expf(-2.0f * ls);
        g_a[i]  = a;
        g_ms[i] = m * a;
        acc += -0.9189385332046727f - ls - 0.5f * m * m * a;
    }
    g_bias[b * TX + x] = acc;
}

// ---------------- kernel 2: pre_out (transposes + attn zero-fill) ----------------
#define NFILL 112
__global__ void __launch_bounds__(512) pre_out(const float* __restrict__ z,
                                               const float* __restrict__ om,
                                               const float* __restrict__ ols,
                                               const int* __restrict__ ylen,
                                               float* __restrict__ out) {
    __shared__ float tile[CC * 129];
    int bid = blockIdx.x;
    int tid = threadIdx.x;
    if (bid < 384) {
        int role, idx;
        const float* src;
        int srcN;
        if (bid < 256)      { role = 0; idx = bid;       src = z;   srcN = TY; }
        else if (bid < 320) { role = 1; idx = bid - 256; src = om;  srcN = TX; }
        else                { role = 2; idx = bid - 320; src = ols; srcN = TX; }
        int tilesPerB = (role == 0) ? 16 : 4;
        int b  = idx / tilesPerB;
        int n0 = (idx % tilesPerB) * 128;
        int tyL = ylen[b];
#pragma unroll
        for (int i = 0; i < 5; ++i) {
            int f  = tid + i * 512;
            int c  = f >> 5;
            int s4 = (f & 31) << 2;
            float4 v = *(const float4*)&src[((size_t)b * CC + c) * srcN + n0 + s4];
            int base = c * 129 + s4;
            tile[base]     = v.x;
            tile[base + 1] = v.y;
            tile[base + 2] = v.z;
            tile[base + 3] = v.w;
        }
        __syncthreads();
#pragma unroll
        for (int i = 0; i < 5; ++i) {
            int f  = tid + i * 512;
            int sl = f / 20;
            int c4 = (f % 20) * 4;
            float4 o;
            o.x = tile[(c4 + 0) * 129 + sl];
            o.y = tile[(c4 + 1) * 129 + sl];
            o.z = tile[(c4 + 2) * 129 + sl];
            o.w = tile[(c4 + 3) * 129 + sl];
            int n = n0 + sl;
            if (role == 0) {
                if (n >= tyL) o = make_float4(0.f, 0.f, 0.f, 0.f);
                *(float4*)&out[OFF_Z + ((size_t)b * TY + n) * CC + c4] = o;
            } else {
                float* dst = (role == 1) ? g_omT : g_olsT;
                *(float4*)&dst[((size_t)b * TX + n) * CC + c4] = o;
            }
        }
    } else {
        size_t total = (size_t)BB * TY * TX / 4;
        float4* p = (float4*)&out[OFF_AT];
        float4 zv = make_float4(0.f, 0.f, 0.f, 0.f);
        size_t start = (size_t)(bid - 384) * 512 + tid;
        for (size_t i = start; i < total; i += (size_t)NFILL * 512)
            p[i] = zv;
    }
}

// ---------------- kernel 3: logp GEMM (f32x2, dup-A smem, 128x128 tile) ----------------
#define GEMM_SMEM 49152
__global__ void __launch_bounds__(256, 2) gemm_logp(const float* __restrict__ z,
                                                    const int* __restrict__ xlen,
                                                    const int* __restrict__ ylen) {
    extern __shared__ __align__(16) unsigned char gsm[];
    unsigned char* smA  = gsm;
    unsigned char* smM  = gsm + 16384;
    unsigned char* smZ1 = gsm + 32768;
    unsigned char* smZ2 = gsm + 40960;

    int b  = blockIdx.z;
    int x0 = blockIdx.x * 128;
    int y0 = blockIdx.y * 128;
    int tid = threadIdx.x;
    int txi = tid & 15;
    int tyi = tid >> 4;
    int xl = txi * 8;
    int yl = tyi * 8;

    unsigned aoff[4];
#pragma unroll
    for (int g = 0; g < 4; ++g) aoff[g] = swz((unsigned)(txi * 64 + g * 16));
    unsigned zoff = (unsigned)(tyi * 32);

    unsigned long long acc[8][4];   // [x_local][y_pair]
#pragma unroll
    for (int i = 0; i < 8; ++i)
#pragma unroll
        for (int j = 0; j < 4; ++j) acc[i][j] = 0ULL;

    for (int kc = 0; kc < CC; kc += 16) {
        __syncthreads();
#pragma unroll
        for (int i = 0; i < 2; ++i) {
            int f  = tid + i * 256;
            int r  = f >> 5;
            int c4 = (f & 31) << 2;
            size_t gi = ((size_t)b * CC + kc + r) * TX + x0 + c4;
            float4 av = *(const float4*)&g_a[gi];
            float4 mv = *(const float4*)&g_ms[gi];
            unsigned sb0 = swz((unsigned)(c4 * 8));
            unsigned sb1 = swz((unsigned)(c4 * 8 + 16));
            *(ulonglong2*)(smA + r * 1024 + sb0) = make_ulonglong2(pack2(av.x, av.x), pack2(av.y, av.y));
            *(ulonglong2*)(smA + r * 1024 + sb1) = make_ulonglong2(pack2(av.z, av.z), pack2(av.w, av.w));
            *(ulonglong2*)(smM + r * 1024 + sb0) = make_ulonglong2(pack2(mv.x, mv.x), pack2(mv.y, mv.y));
            *(ulonglong2*)(smM + r * 1024 + sb1) = make_ulonglong2(pack2(mv.z, mv.z), pack2(mv.w, mv.w));
        }
#pragma unroll
        for (int i = 0; i < 2; ++i) {
            int f  = tid + i * 256;
            int r  = f >> 5;
            int c4 = (f & 31) << 2;
            size_t gi = ((size_t)b * CC + kc + r) * TY + y0 + c4;
            float4 zv = *(const float4*)&z[gi];
            ulonglong2* p1 = (ulonglong2*)(smZ1 + r * 512 + (f & 31) * 16);
            ulonglong2* p2 = (ulonglong2*)(smZ2 + r * 512 + (f & 31) * 16);
            *p1 = make_ulonglong2(pack2(zv.x, zv.y), pack2(zv.z, zv.w));
            *p2 = make_ulonglong2(pack2(-0.5f * zv.x * zv.x, -0.5f * zv.y * zv.y),
                                  pack2(-0.5f * zv.z * zv.z, -0.5f * zv.w * zv.w));
        }
        __syncthreads();
#pragma unroll
        for (int k = 0; k < 16; ++k) {
            const unsigned char* rowA = smA + k * 1024;
            const unsigned char* rowM = smM + k * 1024;
            ulonglong2 z1a = *(const ulonglong2*)(smZ1 + k * 512 + zoff);
            ulonglong2 z1b = *(const ulonglong2*)(smZ1 + k * 512 + zoff + 16);
            ulonglong2 z2a = *(const ulonglong2*)(smZ2 + k * 512 + zoff);
            ulonglong2 z2b = *(const ulonglong2*)(smZ2 + k * 512 + zoff + 16);
            unsigned long long z1p[4] = {z1a.x, z1a.y, z1b.x, z1b.y};
            unsigned long long z2p[4] = {z2a.x, z2a.y, z2b.x, z2b.y};
#pragma unroll
            for (int g = 0; g < 4; ++g) {
                ulonglong2 a2 = *(const ulonglong2*)(rowA + aoff[g]);
                ulonglong2 m2 = *(const ulonglong2*)(rowM + aoff[g]);
#pragma unroll
                for (int yp = 0; yp < 4; ++yp) {
                    acc[2 * g][yp]     = fma2(a2.x, z2p[yp], acc[2 * g][yp]);
                    acc[2 * g][yp]     = fma2(m2.x, z1p[yp], acc[2 * g][yp]);
                    acc[2 * g + 1][yp] = fma2(a2.y, z2p[yp], acc[2 * g + 1][yp]);
                    acc[2 * g + 1][yp] = fma2(m2.y, z1p[yp], acc[2 * g + 1][yp]);
                }
            }
        }
    }

    int txL = xlen[b], tyL = ylen[b];
    float bv[8];
    *(float4*)&bv[0] = *(const float4*)&g_bias[b * TX + x0 + xl];
    *(float4*)&bv[4] = *(const float4*)&g_bias[b * TX + x0 + xl + 4];
#pragma unroll
    for (int yy = 0; yy < 8; ++yy) {
        int y = y0 + yl + yy;
        bool yok = (y < tyL);
        int yp = yy >> 1;
        bool hi = (yy & 1);
        float o[8];
#pragma unroll
        for (int j = 0; j < 8; ++j) {
            float2 u = unpack2(acc[j][yp]);
            float v = hi ? u.y : u.x;
            int x = x0 + xl + j;
            o[j] = (yok && x < txL) ? (bv[j] + v) : 0.0f;
        }
        size_t base = ((size_t)b * TY + y) * TX + x0 + xl;
        *(float4*)&g_logp[base]     = make_float4(o[0], o[1], o[2], o[3]);
        *(float4*)&g_logp[base + 4] = make_float4(o[4], o[5], o[6], o[7]);
    }
}

// ---------------- kernel 4: DP forward (4-warp systolic + cp.async ring) ----------------
// smem: sd[TY*16] u32 128KB | bnd[DPW][TY] 32KB | sxs[TY] 8KB | ring[RINGD][128] float4 32KB
#define DPW 4
#define CHUNK 16
#define RINGD 16
#define FWD_SMEM (TY * 16 * 4 + DPW * TY * 4 + TY * 4 + RINGD * 128 * 16)

__global__ void __launch_bounds__(128) fwd_kernel(const int* __restrict__ xlen,
                                                  const int* __restrict__ ylen,
                                                  float* __restrict__ out) {
    extern __shared__ unsigned char fsm[];
    unsigned* sd = (unsigned*)fsm;                               // [TY][16]
    float* bnd = (float*)(fsm + (size_t)TY * 16 * 4);            // [DPW][TY]
    int* sxs = (int*)(fsm + (size_t)TY * 16 * 4 + DPW * TY * 4); // [TY]
    float4* ring = (float4*)(fsm + (size_t)TY * 16 * 4 + DPW * TY * 4 + TY * 4);

    int b = blockIdx.x;
    int tid = threadIdx.x;
    int w = tid >> 5, lane = tid & 31;
    const float4* lp4 = (const float4*)&g_logp[(size_t)b * TY * TX];
    int gx0 = tid * 4;                      // global x of element 0
    float* mybnd = bnd + w * TY;
    const float* pbnd = bnd + (w - 1) * TY;

    unsigned rbase = (unsigned)__cvta_generic_to_shared(ring) + tid * 16;

    // prime the ring: one commit group per column
#pragma unroll
    for (int d = 0; d < RINGD; ++d) {
        cp16(rbase + d * 2048, &lp4[d * 128 + tid]);
        CP_COMMIT();
    }

    float r0 = NEGF, r1 = NEGF, r2 = NEGF, r3 = NEGF;

    for (int c = 0; c < TY / CHUNK; ++c) {
        if (w > 0) asm volatile("bar.sync %0, 64;" :: "r"(8 + w));
#pragma unroll
        for (int j = 0; j < CHUNK; ++j) {
            int y = c * CHUNK + j;
            CP_WAIT(RINGD - 1);                         // column y's group complete
            float4 cc = ring[(y & (RINGD - 1)) * 128 + tid];
            if (y + RINGD < TY)
                cp16(rbase + (y & (RINGD - 1)) * 2048, &lp4[(size_t)(y + RINGD) * 128 + tid]);
            CP_COMMIT();                                // keep group accounting aligned
            if (y == 0) {
                r0 = (gx0 == 0) ? cc.x : NEGF;
                r1 = r2 = r3 = NEGF;
                if (lane == 31) mybnd[0] = r3;
            } else {
                float left = __shfl_up_sync(0xffffffffu, r3, 1);
                if (lane == 0) left = (w == 0) ? NEGF : pbnd[y - 1];
                bool c1 = r0 > r1, c2 = r1 > r2, c3 = r2 > r3;
                r3 = cc.w + fmaxf(r3, r2);
                r2 = cc.z + fmaxf(r2, r1);
                r1 = cc.y + fmaxf(r1, r0);
                bool c0 = left > r0;
                r0 = cc.x + fmaxf(r0, left);
                unsigned B0 = __ballot_sync(0xffffffffu, c0);
                unsigned B1 = __ballot_sync(0xffffffffu, c1);
                unsigned B2 = __ballot_sync(0xffffffffu, c2);
                unsigned B3 = __ballot_sync(0xffffffffu, c3);
                if (lane == 0)
                    *(uint4*)&sd[(y - 1) * 16 + w * 4] = make_uint4(B0, B1, B2, B3);
                if (lane == 31) mybnd[y] = r3;
            }
        }
        if (w < DPW - 1) asm volatile("bar.sync %0, 64;" :: "r"(9 + w));
    }
    __syncthreads();

    int txL = xlen[b], tyL = ylen[b];
    if (tid == 0) {
        int idx = txL - 1;
        for (int y = tyL - 1; y >= 0; --y) {
            sxs[y] = idx;
            int mv = 0;
            if (idx > 0) {
                if (idx == y) {
                    mv = 1;
                } else {
                    unsigned word = sd[(y - 1) * 16 + ((idx >> 7) << 2) + (idx & 3)];
                    mv = (word >> ((idx >> 2) & 31)) & 1;
                }
            }
            idx -= mv;
        }
    }
    __syncthreads();
    // publish xs
    for (int y = tid; y < tyL; y += 128) g_xs[b * TY + y] = sxs[y];
    for (int y = tyL + tid; y < TY; y += 128) g_xs[b * TY + y] = -1;
    // durations via binary search over monotone sxs[0..tyL)
#pragma unroll
    for (int h = 0; h < 4; ++h) {
        int x = h * 128 + tid;
        float dv = 0.0f;
        if (x < txL) {
            int lo = 0, hi = tyL;
            while (lo < hi) { int mid = (lo + hi) >> 1; if (sxs[mid] < x) lo = mid + 1; else hi = mid; }
            int start = lo;
            hi = tyL;
            while (lo < hi) { int mid = (lo + hi) >> 1; if (sxs[mid] < x + 1) lo = mid + 1; else hi = mid; }
            dv = log1pf((float)(lo - start));
        }
        out[OFF_DUR + b * TX + x] = dv;
    }
}

// ---------------- kernel 5: gathers + attn ones ----------------
__global__ void __launch_bounds__(256) gather_kernel(float* __restrict__ out) {
    int t = blockIdx.x * 256 + threadIdx.x;
    if (t >= BB * TY * 20) return;
    int bs = t / 20;
    int c4 = (t % 20) * 4;
    int b  = bs >> 11;
    int xs = g_xs[bs];
    float4 m = make_float4(0.f, 0.f, 0.f, 0.f), l = m;
    if (xs >= 0) {
        size_t rb = ((size_t)b * TX + xs) * CC + c4;
        m = *(const float4*)&g_omT[rb];
        l = *(const float4*)&g_olsT[rb];
        if (c4 == 0) out[OFF_AT + (size_t)bs * TX + xs] = 1.0f;
    }
    *(float4*)&out[OFF_M + (size_t)bs * CC + c4] = m;
    *(float4*)&out[OFF_L + (size_t)bs * CC + c4] = l;
}

// ---------------- launch ----------------
extern "C" void kernel_launch(void* const* d_in, const int* in_sizes, int n_in,
                              void* d_out, int out_size) {
    const float* om   = (const float*)d_in[0];
    const float* ols  = (const float*)d_in[1];
    const float* z    = (const float*)d_in[2];
    const int*   xlen = (const int*)d_in[3];
    const int*   ylen = (const int*)d_in[4];
    float* out = (float*)d_out;

    static bool attr_set = false;
    if (!attr_set) {
        cudaFuncSetAttribute(fwd_kernel, cudaFuncAttributeMaxDynamicSharedMemorySize, FWD_SMEM);
        cudaFuncSetAttribute(gemm_logp, cudaFuncAttributeMaxDynamicSharedMemorySize, GEMM_SMEM);
        attr_set = true;
    }

    prep_kernel<<<dim3(TX / 128, BB), 128>>>(om, ols);
    pre_out<<<496, 512>>>(z, om, ols, ylen, out);
    gemm_logp<<<dim3(TX / 128, TY / 128, BB), 256, GEMM_SMEM>>>(z, xlen, ylen);
    fwd_kernel<<<BB, DPW * 32, FWD_SMEM>>>(xlen, ylen, out);
    gather_kernel<<<(BB * TY * 20 + 255) / 256, 256>>>(out);
}

// round 9
// speedup vs baseline: 2.0073x; 1.0231x over previous
#include <cuda_runtime.h>
#include <cstdint>

#define BB 16
#define CC 80
#define TX 512
#define TY 2048
#define NEGF (-1000000000.0f)

// Output layout (flat concat, fp32):
// z_T [B,TY,C], y_mean_T [B,TY,C], y_ls_T [B,TY,C], attn_T [B,TY,TX], dur [B,TX,1]
#define N_ZT   ((size_t)BB * TY * CC)
#define OFF_Z   ((size_t)0)
#define OFF_M   (N_ZT)
#define OFF_L   (2 * N_ZT)
#define OFF_AT  (3 * N_ZT)
#define OFF_DUR (3 * N_ZT + (size_t)BB * TY * TX)

// ---------------- scratch ----------------
__device__ float g_a   [BB * CC * TX];
__device__ float g_ms  [BB * CC * TX];
__device__ float g_bias[BB * TX];
__device__ float g_logp[(size_t)BB * TY * TX];
__device__ int   g_xs  [BB * TY];
__device__ float g_omT [BB * TX * CC];   // [b][x][c]
__device__ float g_olsT[BB * TX * CC];

// ---------------- f32x2 helpers ----------------
__device__ __forceinline__ unsigned long long pack2(float lo, float hi) {
    unsigned long long r;
    asm("mov.b64 %0, {%1, %2};" : "=l"(r) : "f"(lo), "f"(hi));
    return r;
}
__device__ __forceinline__ float2 unpack2(unsigned long long v) {
    float lo, hi;
    asm("mov.b64 {%0, %1}, %2;" : "=f"(lo), "=f"(hi) : "l"(v));
    return make_float2(lo, hi);
}
__device__ __forceinline__ unsigned long long fma2(unsigned long long a,
                                                   unsigned long long b,
                                                   unsigned long long c) {
    unsigned long long d;
    asm("fma.rn.f32x2 %0, %1, %2, %3;" : "=l"(d) : "l"(a), "l"(b), "l"(c));
    return d;
}
__device__ __forceinline__ unsigned swz(unsigned b) {
    return b ^ ((b >> 3) & 0x70u);
}
__device__ __forceinline__ void cp16(unsigned smem_addr, const void* gptr) {
    asm volatile("cp.async.ca.shared.global [%0], [%1], 16;\n"
                 :: "r"(smem_addr), "l"(gptr));
}
#define CP_COMMIT() asm volatile("cp.async.commit_group;\n" ::: "memory")
#define CP_WAIT(n)  asm volatile("cp.async.wait_group %0;\n" :: "n"(n) : "memory")

// ---------------- kernel 1: prep ----------------
__global__ void __launch_bounds__(128) prep_kernel(const float* __restrict__ om,
                                                   const float* __restrict__ ols) {
    int b = blockIdx.y;
    int x = blockIdx.x * 128 + threadIdx.x;
    float acc = 0.0f;
    for (int c = 0; c < CC; ++c) {
        size_t i = ((size_t)b * CC + c) * TX + x;
        float ls = ols[i];
        float m  = om[i];
        float a  = expf(-2.0f * ls);
        g_a[i]  = a;
        g_ms[i] = m * a;
        acc += -0.9189385332046727f - ls - 0.5f * m * m * a;
    }
    g_bias[b * TX + x] = acc;
}

// ---------------- kernel 2: pre_out (transposes + attn zero-fill) ----------------
#define NFILL 112
__global__ void __launch_bounds__(512) pre_out(const float* __restrict__ z,
                                               const float* __restrict__ om,
                                               const float* __restrict__ ols,
                                               const int* __restrict__ ylen,
                                               float* __restrict__ out) {
    __shared__ float tile[CC * 129];
    int bid = blockIdx.x;
    int tid = threadIdx.x;
    if (bid < 384) {
        int role, idx;
        const float* src;
        int srcN;
        if (bid < 256)      { role = 0; idx = bid;       src = z;   srcN = TY; }
        else if (bid < 320) { role = 1; idx = bid - 256; src = om;  srcN = TX; }
        else                { role = 2; idx = bid - 320; src = ols; srcN = TX; }
        int tilesPerB = (role == 0) ? 16 : 4;
        int b  = idx / tilesPerB;
        int n0 = (idx % tilesPerB) * 128;
        int tyL = ylen[b];
#pragma unroll
        for (int i = 0; i < 5; ++i) {
            int f  = tid + i * 512;
            int c  = f >> 5;
            int s4 = (f & 31) << 2;
            float4 v = *(const float4*)&src[((size_t)b * CC + c) * srcN + n0 + s4];
            int base = c * 129 + s4;
            tile[base]     = v.x;
            tile[base + 1] = v.y;
            tile[base + 2] = v.z;
            tile[base + 3] = v.w;
        }
        __syncthreads();
#pragma unroll
        for (int i = 0; i < 5; ++i) {
            int f  = tid + i * 512;
            int sl = f / 20;
            int c4 = (f % 20) * 4;
            float4 o;
            o.x = tile[(c4 + 0) * 129 + sl];
            o.y = tile[(c4 + 1) * 129 + sl];
            o.z = tile[(c4 + 2) * 129 + sl];
            o.w = tile[(c4 + 3) * 129 + sl];
            int n = n0 + sl;
            if (role == 0) {
                if (n >= tyL) o = make_float4(0.f, 0.f, 0.f, 0.f);
                *(float4*)&out[OFF_Z + ((size_t)b * TY + n) * CC + c4] = o;
            } else {
                float* dst = (role == 1) ? g_omT : g_olsT;
                *(float4*)&dst[((size_t)b * TX + n) * CC + c4] = o;
            }
        }
    } else {
        size_t total = (size_t)BB * TY * TX / 4;
        float4* p = (float4*)&out[OFF_AT];
        float4 zv = make_float4(0.f, 0.f, 0.f, 0.f);
        size_t start = (size_t)(bid - 384) * 512 + tid;
        for (size_t i = start; i < total; i += (size_t)NFILL * 512)
            p[i] = zv;
    }
}

// ---------------- kernel 3: logp GEMM (f32x2, dup-A smem, 128x128 tile) ----------------
#define GEMM_SMEM 49152
__global__ void __launch_bounds__(256, 2) gemm_logp(const float* __restrict__ z,
                                                    const int* __restrict__ xlen,
                                                    const int* __restrict__ ylen) {
    extern __shared__ __align__(16) unsigned char gsm[];
    unsigned char* smA  = gsm;
    unsigned char* smM  = gsm + 16384;
    unsigned char* smZ1 = gsm + 32768;
    unsigned char* smZ2 = gsm + 40960;

    int b  = blockIdx.z;
    int x0 = blockIdx.x * 128;
    int y0 = blockIdx.y * 128;
    int tid = threadIdx.x;
    int txi = tid & 15;
    int tyi = tid >> 4;
    int xl = txi * 8;
    int yl = tyi * 8;

    unsigned aoff[4];
#pragma unroll
    for (int g = 0; g < 4; ++g) aoff[g] = swz((unsigned)(txi * 64 + g * 16));
    unsigned zoff = (unsigned)(tyi * 32);

    unsigned long long acc[8][4];   // [x_local][y_pair]
#pragma unroll
    for (int i = 0; i < 8; ++i)
#pragma unroll
        for (int j = 0; j < 4; ++j) acc[i][j] = 0ULL;

    for (int kc = 0; kc < CC; kc += 16) {
        __syncthreads();
#pragma unroll
        for (int i = 0; i < 2; ++i) {
            int f  = tid + i * 256;
            int r  = f >> 5;
            int c4 = (f & 31) << 2;
            size_t gi = ((size_t)b * CC + kc + r) * TX + x0 + c4;
            float4 av = *(const float4*)&g_a[gi];
            float4 mv = *(const float4*)&g_ms[gi];
            unsigned sb0 = swz((unsigned)(c4 * 8));
            unsigned sb1 = swz((unsigned)(c4 * 8 + 16));
            *(ulonglong2*)(smA + r * 1024 + sb0) = make_ulonglong2(pack2(av.x, av.x), pack2(av.y, av.y));
            *(ulonglong2*)(smA + r * 1024 + sb1) = make_ulonglong2(pack2(av.z, av.z), pack2(av.w, av.w));
            *(ulonglong2*)(smM + r * 1024 + sb0) = make_ulonglong2(pack2(mv.x, mv.x), pack2(mv.y, mv.y));
            *(ulonglong2*)(smM + r * 1024 + sb1) = make_ulonglong2(pack2(mv.z, mv.z), pack2(mv.w, mv.w));
        }
#pragma unroll
        for (int i = 0; i < 2; ++i) {
            int f  = tid + i * 256;
            int r  = f >> 5;
            int c4 = (f & 31) << 2;
            size_t gi = ((size_t)b * CC + kc + r) * TY + y0 + c4;
            float4 zv = *(const float4*)&z[gi];
            ulonglong2* p1 = (ulonglong2*)(smZ1 + r * 512 + (f & 31) * 16);
            ulonglong2* p2 = (ulonglong2*)(smZ2 + r * 512 + (f & 31) * 16);
            *p1 = make_ulonglong2(pack2(zv.x, zv.y), pack2(zv.z, zv.w));
            *p2 = make_ulonglong2(pack2(-0.5f * zv.x * zv.x, -0.5f * zv.y * zv.y),
                                  pack2(-0.5f * zv.z * zv.z, -0.5f * zv.w * zv.w));
        }
        __syncthreads();
#pragma unroll
        for (int k = 0; k < 16; ++k) {
            const unsigned char* rowA = smA + k * 1024;
            const unsigned char* rowM = smM + k * 1024;
            ulonglong2 z1a = *(const ulonglong2*)(smZ1 + k * 512 + zoff);
            ulonglong2 z1b = *(const ulonglong2*)(smZ1 + k * 512 + zoff + 16);
            ulonglong2 z2a = *(const ulonglong2*)(smZ2 + k * 512 + zoff);
            ulonglong2 z2b = *(const ulonglong2*)(smZ2 + k * 512 + zoff + 16);
            unsigned long long z1p[4] = {z1a.x, z1a.y, z1b.x, z1b.y};
            unsigned long long z2p[4] = {z2a.x, z2a.y, z2b.x, z2b.y};
#pragma unroll
            for (int g = 0; g < 4; ++g) {
                ulonglong2 a2 = *(const ulonglong2*)(rowA + aoff[g]);
                ulonglong2 m2 = *(const ulonglong2*)(rowM + aoff[g]);
#pragma unroll
                for (int yp = 0; yp < 4; ++yp) {
                    acc[2 * g][yp]     = fma2(a2.x, z2p[yp], acc[2 * g][yp]);
                    acc[2 * g][yp]     = fma2(m2.x, z1p[yp], acc[2 * g][yp]);
                    acc[2 * g + 1][yp] = fma2(a2.y, z2p[yp], acc[2 * g + 1][yp]);
                    acc[2 * g + 1][yp] = fma2(m2.y, z1p[yp], acc[2 * g + 1][yp]);
                }
            }
        }
    }

    int txL = xlen[b], tyL = ylen[b];
    float bv[8];
    *(float4*)&bv[0] = *(const float4*)&g_bias[b * TX + x0 + xl];
    *(float4*)&bv[4] = *(const float4*)&g_bias[b * TX + x0 + xl + 4];
#pragma unroll
    for (int yy = 0; yy < 8; ++yy) {
        int y = y0 + yl + yy;
        bool yok = (y < tyL);
        int yp = yy >> 1;
        bool hi = (yy & 1);
        float o[8];
#pragma unroll
        for (int j = 0; j < 8; ++j) {
            float2 u = unpack2(acc[j][yp]);
            float v = hi ? u.y : u.x;
            int x = x0 + xl + j;
            o[j] = (yok && x < txL) ? (bv[j] + v) : 0.0f;
        }
        size_t base = ((size_t)b * TY + y) * TX + x0 + xl;
        *(float4*)&g_logp[base]     = make_float4(o[0], o[1], o[2], o[3]);
        *(float4*)&g_logp[base + 4] = make_float4(o[4], o[5], o[6], o[7]);
    }
}

// ---------------- kernel 4: DP forward (4-warp systolic, 4-col cp.async groups) ----------------
// smem: sd[TY*16] u32 128KB | bnd[DPW][TY] 32KB | sxs[TY] 8KB | ring[16][128] float4 32KB
#define DPW 4
#define CHUNK 16
#define RINGC 16          // ring depth in columns
#define FWD_SMEM (TY * 16 * 4 + DPW * TY * 4 + TY * 4 + RINGC * 128 * 16)

__global__ void __launch_bounds__(128) fwd_kernel(const int* __restrict__ xlen,
                                                  const int* __restrict__ ylen,
                                                  float* __restrict__ out) {
    extern __shared__ unsigned char fsm[];
    unsigned* sd = (unsigned*)fsm;                               // [TY][16]
    float* bnd = (float*)(fsm + (size_t)TY * 16 * 4);            // [DPW][TY]
    int* sxs = (int*)(fsm + (size_t)TY * 16 * 4 + DPW * TY * 4); // [TY]
    float4* ring = (float4*)(fsm + (size_t)TY * 16 * 4 + DPW * TY * 4 + TY * 4);

    int b = blockIdx.x;
    int tid = threadIdx.x;
    int w = tid >> 5, lane = tid & 31;
    const float4* lp4 = (const float4*)&g_logp[(size_t)b * TY * TX];
    int gx0 = tid * 4;
    float* mybnd = bnd + w * TY;
    const float* pbnd = bnd + (w - 1) * TY;

    unsigned rbase = (unsigned)__cvta_generic_to_shared(ring) + tid * 16;

    // prime: 4 groups of 4 columns
#pragma unroll
    for (int d = 0; d < 4; ++d) {
#pragma unroll
        for (int q = 0; q < 4; ++q)
            cp16(rbase + (d * 4 + q) * 2048, &lp4[(d * 4 + q) * 128 + tid]);
        CP_COMMIT();
    }

    float r0 = NEGF, r1 = NEGF, r2 = NEGF, r3 = NEGF;

    for (int c = 0; c < TY / CHUNK; ++c) {
        if (w > 0) asm volatile("bar.sync %0, 64;" :: "r"(8 + w));
#pragma unroll
        for (int g = 0; g < 4; ++g) {
            int y0 = c * CHUNK + g * 4;
            CP_WAIT(3);
            // read the 4 columns of this group (latencies overlap)
            float4 cc0 = ring[((y0 + 0) & (RINGC - 1)) * 128 + tid];
            float4 cc1 = ring[((y0 + 1) & (RINGC - 1)) * 128 + tid];
            float4 cc2 = ring[((y0 + 2) & (RINGC - 1)) * 128 + tid];
            float4 cc3 = ring[((y0 + 3) & (RINGC - 1)) * 128 + tid];
            // prev-warp boundary values, loaded off the critical path (broadcast)
            float pb[4];
#pragma unroll
            for (int q = 0; q < 4; ++q) {
                int yi = y0 + q - 1;
                pb[q] = (w > 0 && yi >= 0) ? pbnd[yi] : NEGF;
            }
            // prefetch group 4 ahead (same ring slots)
            if (c + 1 < TY / CHUNK) {
#pragma unroll
                for (int q = 0; q < 4; ++q)
                    cp16(rbase + ((y0 + q) & (RINGC - 1)) * 2048,
                         &lp4[(size_t)(y0 + RINGC + q) * 128 + tid]);
            }
            CP_COMMIT();
            // 4 columns of DP
#pragma unroll
            for (int j = 0; j < 4; ++j) {
                int y = y0 + j;
                float4 cc = (j == 0) ? cc0 : (j == 1) ? cc1 : (j == 2) ? cc2 : cc3;
                if (y == 0) {
                    r0 = (gx0 == 0) ? cc.x : NEGF;
                    r1 = r2 = r3 = NEGF;
                    if (lane == 31) mybnd[0] = r3;
                } else {
                    float left = __shfl_up_sync(0xffffffffu, r3, 1);
                    if (lane == 0) left = pb[j];
                    bool c1 = r0 > r1, c2 = r1 > r2, c3 = r2 > r3;
                    r3 = cc.w + fmaxf(r3, r2);
                    r2 = cc.z + fmaxf(r2, r1);
                    r1 = cc.y + fmaxf(r1, r0);
                    bool c0 = left > r0;
                    r0 = cc.x + fmaxf(r0, left);
                    unsigned B0 = __ballot_sync(0xffffffffu, c0);
                    unsigned B1 = __ballot_sync(0xffffffffu, c1);
                    unsigned B2 = __ballot_sync(0xffffffffu, c2);
                    unsigned B3 = __ballot_sync(0xffffffffu, c3);
                    if (lane == 0)
                        *(uint4*)&sd[(y - 1) * 16 + w * 4] = make_uint4(B0, B1, B2, B3);
                    if (lane == 31) mybnd[y] = r3;
                }
            }
        }
        if (w < DPW - 1) asm volatile("bar.sync %0, 64;" :: "r"(9 + w));
    }
    __syncthreads();

    int txL = xlen[b], tyL = ylen[b];
    if (tid == 0) {
        int idx = txL - 1;
        for (int y = tyL - 1; y >= 0; --y) {
            sxs[y] = idx;
            int mv = 0;
            if (idx > 0) {
                if (idx == y) {
                    mv = 1;
                } else {
                    unsigned word = sd[(y - 1) * 16 + ((idx >> 7) << 2) + (idx & 3)];
                    mv = (word >> ((idx >> 2) & 31)) & 1;
                }
            }
            idx -= mv;
        }
    }
    __syncthreads();
    // publish xs
    for (int y = tid; y < tyL; y += 128) g_xs[b * TY + y] = sxs[y];
    for (int y = tyL + tid; y < TY; y += 128) g_xs[b * TY + y] = -1;
    // durations via binary search over monotone sxs[0..tyL)
#pragma unroll
    for (int h = 0; h < 4; ++h) {
        int x = h * 128 + tid;
        float dv = 0.0f;
        if (x < txL) {
            int lo = 0, hi = tyL;
            while (lo < hi) { int mid = (lo + hi) >> 1; if (sxs[mid] < x) lo = mid + 1; else hi = mid; }
            int start = lo;
            hi = tyL;
            while (lo < hi) { int mid = (lo + hi) >> 1; if (sxs[mid] < x + 1) lo = mid + 1; else hi = mid; }
            dv = log1pf((float)(lo - start));
        }
        out[OFF_DUR + b * TX + x] = dv;
    }
}

// ---------------- kernel 5: gathers + attn ones ----------------
__global__ void __launch_bounds__(256) gather_kernel(float* __restrict__ out) {
    int t = blockIdx.x * 256 + threadIdx.x;
    if (t >= BB * TY * 20) return;
    int bs = t / 20;
    int c4 = (t % 20) * 4;
    int b  = bs >> 11;
    int xs = g_xs[bs];
    float4 m = make_float4(0.f, 0.f, 0.f, 0.f), l = m;
    if (xs >= 0) {
        size_t rb = ((size_t)b * TX + xs) * CC + c4;
        m = *(const float4*)&g_omT[rb];
        l = *(const float4*)&g_olsT[rb];
        if (c4 == 0) out[OFF_AT + (size_t)bs * TX + xs] = 1.0f;
    }
    *(float4*)&out[OFF_M + (size_t)bs * CC + c4] = m;
    *(float4*)&out[OFF_L + (size_t)bs * CC + c4] = l;
}

// ---------------- launch ----------------
extern "C" void kernel_launch(void* const* d_in, const int* in_sizes, int n_in,
                              void* d_out, int out_size) {
    const float* om   = (const float*)d_in[0];
    const float* ols  = (const float*)d_in[1];
    const float* z    = (const float*)d_in[2];
    const int*   xlen = (const int*)d_in[3];
    const int*   ylen = (const int*)d_in[4];
    float* out = (float*)d_out;

    static bool attr_set = false;
    if (!attr_set) {
        cudaFuncSetAttribute(fwd_kernel, cudaFuncAttributeMaxDynamicSharedMemorySize, FWD_SMEM);
        cudaFuncSetAttribute(gemm_logp, cudaFuncAttributeMaxDynamicSharedMemorySize, GEMM_SMEM);
        attr_set = true;
    }

    prep_kernel<<<dim3(TX / 128, BB), 128>>>(om, ols);
    pre_out<<<496, 512>>>(z, om, ols, ylen, out);
    gemm_logp<<<dim3(TX / 128, TY / 128, BB), 256, GEMM_SMEM>>>(z, xlen, ylen);
    fwd_kernel<<<BB, DPW * 32, FWD_SMEM>>>(xlen, ylen, out);
    gather_kernel<<<(BB * TY * 20 + 255) / 256, 256>>>(out);
}

// round 10
// speedup vs baseline: 3.0518x; 1.5204x over previous
#include <cuda_runtime.h>
#include <cstdint>

#define BB 16
#define CC 80
#define TX 512
#define TY 2048
#define NEGF (-1000000000.0f)

// Output layout (flat concat, fp32):
// z_T [B,TY,C], y_mean_T [B,TY,C], y_ls_T [B,TY,C], attn_T [B,TY,TX], dur [B,TX,1]
#define N_ZT   ((size_t)BB * TY * CC)
#define OFF_Z   ((size_t)0)
#define OFF_M   (N_ZT)
#define OFF_L   (2 * N_ZT)
#define OFF_AT  (3 * N_ZT)
#define OFF_DUR (3 * N_ZT + (size_t)BB * TY * TX)

// ---------------- scratch ----------------
__device__ float g_a   [BB * CC * TX];
__device__ float g_ms  [BB * CC * TX];
__device__ float g_bias[BB * TX];
__device__ float g_logp[(size_t)BB * TY * TX];
__device__ int   g_xs  [BB * TY];
__device__ float g_omT [BB * TX * CC];   // [b][x][c]
__device__ float g_olsT[BB * TX * CC];

// ---------------- f32x2 helpers ----------------
__device__ __forceinline__ unsigned long long pack2(float lo, float hi) {
    unsigned long long r;
    asm("mov.b64 %0, {%1, %2};" : "=l"(r) : "f"(lo), "f"(hi));
    return r;
}
__device__ __forceinline__ float2 unpack2(unsigned long long v) {
    float lo, hi;
    asm("mov.b64 {%0, %1}, %2;" : "=f"(lo), "=f"(hi) : "l"(v));
    return make_float2(lo, hi);
}
__device__ __forceinline__ unsigned long long fma2(unsigned long long a,
                                                   unsigned long long b,
                                                   unsigned long long c) {
    unsigned long long d;
    asm("fma.rn.f32x2 %0, %1, %2, %3;" : "=l"(d) : "l"(a), "l"(b), "l"(c));
    return d;
}
__device__ __forceinline__ unsigned swz(unsigned b) {
    return b ^ ((b >> 3) & 0x70u);
}
__device__ __forceinline__ void cp16(unsigned smem_addr, const void* gptr) {
    asm volatile("cp.async.ca.shared.global [%0], [%1], 16;\n"
                 :: "r"(smem_addr), "l"(gptr));
}
#define CP_COMMIT() asm volatile("cp.async.commit_group;\n" ::: "memory")
#define CP_WAIT(n)  asm volatile("cp.async.wait_group %0;\n" :: "n"(n) : "memory")

// ---------------- kernel 1: prep ----------------
__global__ void __launch_bounds__(128) prep_kernel(const float* __restrict__ om,
                                                   const float* __restrict__ ols) {
    int b = blockIdx.y;
    int x = blockIdx.x * 128 + threadIdx.x;
    float acc = 0.0f;
    for (int c = 0; c < CC; ++c) {
        size_t i = ((size_t)b * CC + c) * TX + x;
        float ls = ols[i];
        float m  = om[i];
        float a  = expf(-2.0f * ls);
        g_a[i]  = a;
        g_ms[i] = m * a;
        acc += -0.9189385332046727f - ls - 0.5f * m * m * a;
    }
    g_bias[b * TX + x] = acc;
}

// ---------------- kernel 2: pre_out (transposes + attn zero-fill) ----------------
#define NFILL 112
__global__ void __launch_bounds__(512) pre_out(const float* __restrict__ z,
                                               const float* __restrict__ om,
                                               const float* __restrict__ ols,
                                               const int* __restrict__ ylen,
                                               float* __restrict__ out) {
    __shared__ float tile[CC * 129];
    int bid = blockIdx.x;
    int tid = threadIdx.x;
    if (bid < 384) {
        int role, idx;
        const float* src;
        int srcN;
        if (bid < 256)      { role = 0; idx = bid;       src = z;   srcN = TY; }
        else if (bid < 320) { role = 1; idx = bid - 256; src = om;  srcN = TX; }
        else                { role = 2; idx = bid - 320; src = ols; srcN = TX; }
        int tilesPerB = (role == 0) ? 16 : 4;
        int b  = idx / tilesPerB;
        int n0 = (idx % tilesPerB) * 128;
        int tyL = ylen[b];
#pragma unroll
        for (int i = 0; i < 5; ++i) {
            int f  = tid + i * 512;
            int c  = f >> 5;
            int s4 = (f & 31) << 2;
            float4 v = *(const float4*)&src[((size_t)b * CC + c) * srcN + n0 + s4];
            int base = c * 129 + s4;
            tile[base]     = v.x;
            tile[base + 1] = v.y;
            tile[base + 2] = v.z;
            tile[base + 3] = v.w;
        }
        __syncthreads();
#pragma unroll
        for (int i = 0; i < 5; ++i) {
            int f  = tid + i * 512;
            int sl = f / 20;
            int c4 = (f % 20) * 4;
            float4 o;
            o.x = tile[(c4 + 0) * 129 + sl];
            o.y = tile[(c4 + 1) * 129 + sl];
            o.z = tile[(c4 + 2) * 129 + sl];
            o.w = tile[(c4 + 3) * 129 + sl];
            int n = n0 + sl;
            if (role == 0) {
                if (n >= tyL) o = make_float4(0.f, 0.f, 0.f, 0.f);
                *(float4*)&out[OFF_Z + ((size_t)b * TY + n) * CC + c4] = o;
            } else {
                float* dst = (role == 1) ? g_omT : g_olsT;
                *(float4*)&dst[((size_t)b * TX + n) * CC + c4] = o;
            }
        }
    } else {
        size_t total = (size_t)BB * TY * TX / 4;
        float4* p = (float4*)&out[OFF_AT];
        float4 zv = make_float4(0.f, 0.f, 0.f, 0.f);
        size_t start = (size_t)(bid - 384) * 512 + tid;
        for (size_t i = start; i < total; i += (size_t)NFILL * 512)
            p[i] = zv;
    }
}

// ---------------- kernel 3: logp GEMM (f32x2, dup-A smem, 128x128 tile) ----------------
#define GEMM_SMEM 49152
__global__ void __launch_bounds__(256, 2) gemm_logp(const float* __restrict__ z,
                                                    const int* __restrict__ xlen,
                                                    const int* __restrict__ ylen) {
    extern __shared__ __align__(16) unsigned char gsm[];
    unsigned char* smA  = gsm;
    unsigned char* smM  = gsm + 16384;
    unsigned char* smZ1 = gsm + 32768;
    unsigned char* smZ2 = gsm + 40960;

    int b  = blockIdx.z;
    int x0 = blockIdx.x * 128;
    int y0 = blockIdx.y * 128;
    int tid = threadIdx.x;
    int txi = tid & 15;
    int tyi = tid >> 4;
    int xl = txi * 8;
    int yl = tyi * 8;

    unsigned aoff[4];
#pragma unroll
    for (int g = 0; g < 4; ++g) aoff[g] = swz((unsigned)(txi * 64 + g * 16));
    unsigned zoff = (unsigned)(tyi * 32);

    unsigned long long acc[8][4];   // [x_local][y_pair]
#pragma unroll
    for (int i = 0; i < 8; ++i)
#pragma unroll
        for (int j = 0; j < 4; ++j) acc[i][j] = 0ULL;

    for (int kc = 0; kc < CC; kc += 16) {
        __syncthreads();
#pragma unroll
        for (int i = 0; i < 2; ++i) {
            int f  = tid + i * 256;
            int r  = f >> 5;
            int c4 = (f & 31) << 2;
            size_t gi = ((size_t)b * CC + kc + r) * TX + x0 + c4;
            float4 av = *(const float4*)&g_a[gi];
            float4 mv = *(const float4*)&g_ms[gi];
            unsigned sb0 = swz((unsigned)(c4 * 8));
            unsigned sb1 = swz((unsigned)(c4 * 8 + 16));
            *(ulonglong2*)(smA + r * 1024 + sb0) = make_ulonglong2(pack2(av.x, av.x), pack2(av.y, av.y));
            *(ulonglong2*)(smA + r * 1024 + sb1) = make_ulonglong2(pack2(av.z, av.z), pack2(av.w, av.w));
            *(ulonglong2*)(smM + r * 1024 + sb0) = make_ulonglong2(pack2(mv.x, mv.x), pack2(mv.y, mv.y));
            *(ulonglong2*)(smM + r * 1024 + sb1) = make_ulonglong2(pack2(mv.z, mv.z), pack2(mv.w, mv.w));
        }
#pragma unroll
        for (int i = 0; i < 2; ++i) {
            int f  = tid + i * 256;
            int r  = f >> 5;
            int c4 = (f & 31) << 2;
            size_t gi = ((size_t)b * CC + kc + r) * TY + y0 + c4;
            float4 zv = *(const float4*)&z[gi];
            ulonglong2* p1 = (ulonglong2*)(smZ1 + r * 512 + (f & 31) * 16);
            ulonglong2* p2 = (ulonglong2*)(smZ2 + r * 512 + (f & 31) * 16);
            *p1 = make_ulonglong2(pack2(zv.x, zv.y), pack2(zv.z, zv.w));
            *p2 = make_ulonglong2(pack2(-0.5f * zv.x * zv.x, -0.5f * zv.y * zv.y),
                                  pack2(-0.5f * zv.z * zv.z, -0.5f * zv.w * zv.w));
        }
        __syncthreads();
#pragma unroll
        for (int k = 0; k < 16; ++k) {
            const unsigned char* rowA = smA + k * 1024;
            const unsigned char* rowM = smM + k * 1024;
            ulonglong2 z1a = *(const ulonglong2*)(smZ1 + k * 512 + zoff);
            ulonglong2 z1b = *(const ulonglong2*)(smZ1 + k * 512 + zoff + 16);
            ulonglong2 z2a = *(const ulonglong2*)(smZ2 + k * 512 + zoff);
            ulonglong2 z2b = *(const ulonglong2*)(smZ2 + k * 512 + zoff + 16);
            unsigned long long z1p[4] = {z1a.x, z1a.y, z1b.x, z1b.y};
            unsigned long long z2p[4] = {z2a.x, z2a.y, z2b.x, z2b.y};
#pragma unroll
            for (int g = 0; g < 4; ++g) {
                ulonglong2 a2 = *(const ulonglong2*)(rowA + aoff[g]);
                ulonglong2 m2 = *(const ulonglong2*)(rowM + aoff[g]);
#pragma unroll
                for (int yp = 0; yp < 4; ++yp) {
                    acc[2 * g][yp]     = fma2(a2.x, z2p[yp], acc[2 * g][yp]);
                    acc[2 * g][yp]     = fma2(m2.x, z1p[yp], acc[2 * g][yp]);
                    acc[2 * g + 1][yp] = fma2(a2.y, z2p[yp], acc[2 * g + 1][yp]);
                    acc[2 * g + 1][yp] = fma2(m2.y, z1p[yp], acc[2 * g + 1][yp]);
                }
            }
        }
    }

    int txL = xlen[b], tyL = ylen[b];
    float bv[8];
    *(float4*)&bv[0] = *(const float4*)&g_bias[b * TX + x0 + xl];
    *(float4*)&bv[4] = *(const float4*)&g_bias[b * TX + x0 + xl + 4];
#pragma unroll
    for (int yy = 0; yy < 8; ++yy) {
        int y = y0 + yl + yy;
        bool yok = (y < tyL);
        int yp = yy >> 1;
        bool hi = (yy & 1);
        float o[8];
#pragma unroll
        for (int j = 0; j < 8; ++j) {
            float2 u = unpack2(acc[j][yp]);
            float v = hi ? u.y : u.x;
            int x = x0 + xl + j;
            o[j] = (yok && x < txL) ? (bv[j] + v) : 0.0f;
        }
        size_t base = ((size_t)b * TY + y) * TX + x0 + xl;
        *(float4*)&g_logp[base]     = make_float4(o[0], o[1], o[2], o[3]);
        *(float4*)&g_logp[base + 4] = make_float4(o[4], o[5], o[6], o[7]);
    }
}

// ---------------- kernel 4: DP forward (4-warp systolic, nibble sd, pipelined shfl) ----------------
// smem: sd[TY/8][128] u32 128KB | bndw[DPW][64] 1KB | sxs[TY] 8KB | ring[16][128] float4 32KB
#define DPW 4
#define CHUNK 16
#define RINGC 16
#define SD_WORDS (TY / 8 * 128)
#define FWD_SMEM (SD_WORDS * 4 + DPW * 64 * 4 + TY * 4 + RINGC * 128 * 16)

__global__ void __launch_bounds__(128) fwd_kernel(const int* __restrict__ xlen,
                                                  const int* __restrict__ ylen,
                                                  float* __restrict__ out) {
    extern __shared__ unsigned char fsm[];
    unsigned* sd = (unsigned*)fsm;                                     // [TY/8][128]
    float* bndw = (float*)(fsm + (size_t)SD_WORDS * 4);                // [DPW][64] circular
    int* sxs = (int*)(fsm + (size_t)SD_WORDS * 4 + DPW * 64 * 4);      // [TY]
    float4* ring = (float4*)(fsm + (size_t)SD_WORDS * 4 + DPW * 64 * 4 + TY * 4);

    int b = blockIdx.x;
    int tid = threadIdx.x;
    int w = tid >> 5, lane = tid & 31;
    const float4* lp4 = (const float4*)&g_logp[(size_t)b * TY * TX];
    int gx0 = tid * 4;
    float* mybnd = bndw + w * 64;
    const float* pbnd = bndw + (w - 1) * 64;

    unsigned rbase = (unsigned)__cvta_generic_to_shared(ring) + tid * 16;

    // prime: 2 groups of 8 columns
#pragma unroll
    for (int d = 0; d < 2; ++d) {
#pragma unroll
        for (int q = 0; q < 8; ++q)
            cp16(rbase + (d * 8 + q) * 2048, &lp4[(d * 8 + q) * 128 + tid]);
        CP_COMMIT();
    }

    float r0 = NEGF, r1 = NEGF, r2 = NEGF, r3 = NEGF;
    unsigned nib = 0;

    for (int c = 0; c < TY / CHUNK; ++c) {
        if (w > 0) asm volatile("bar.sync %0, 64;" :: "r"(8 + w));
#pragma unroll
        for (int g = 0; g < 2; ++g) {
            int y0 = c * CHUNK + g * 8;
            CP_WAIT(1);
            float4 cc[8];
#pragma unroll
            for (int q = 0; q < 8; ++q)
                cc[q] = ring[((y0 + q) & (RINGC - 1)) * 128 + tid];
            float pb[8];
#pragma unroll
            for (int q = 0; q < 8; ++q) {
                int yi = y0 + q - 1;
                pb[q] = (w > 0 && yi >= 0) ? pbnd[yi & 63] : NEGF;
            }
            if (y0 + RINGC < TY) {
#pragma unroll
                for (int q = 0; q < 8; ++q)
                    cp16(rbase + ((y0 + q) & (RINGC - 1)) * 2048,
                         &lp4[(size_t)(y0 + RINGC + q) * 128 + tid]);
            }
            CP_COMMIT();
#pragma unroll
            for (int j = 0; j < 8; ++j) {
                int y = y0 + j;
                if (y == 0) {
                    r0 = (gx0 == 0) ? cc[0].x : NEGF;
                    r1 = r2 = r3 = NEGF;
                    if (lane == 31) mybnd[0] = r3;
                } else {
                    float ls = __shfl_up_sync(0xffffffffu, r3, 1);   // issued first
                    bool c3 = r2 > r3; r3 = cc[j].w + fmaxf(r3, r2);
                    bool c2 = r1 > r2; r2 = cc[j].z + fmaxf(r2, r1);
                    bool c1 = r0 > r1; r1 = cc[j].y + fmaxf(r1, r0);
                    float left = (lane == 0) ? pb[j] : ls;           // consume late
                    bool c0 = left > r0;
                    r0 = cc[j].x + fmaxf(r0, left);
                    unsigned nb = (c0 ? 1u : 0u) | (c1 ? 2u : 0u) |
                                  (c2 ? 4u : 0u) | (c3 ? 8u : 0u);
                    if (j == 0) {
                        nib |= nb << 28;                             // nibble index 7 of prev word
                        sd[(c * 2 + g - 1) * 128 + tid] = nib;       // flush row (y-1)>>3
                        nib = 0;
                    } else {
                        nib |= nb << ((j - 1) * 4);
                    }
                    if (lane == 31) mybnd[y & 63] = r3;
                }
            }
        }
        if (w < DPW - 1) asm volatile("bar.sync %0, 64;" :: "r"(9 + w));
    }
    // final partial word (rows for y-1 = 2040..2046)
    sd[(TY / 8 - 1) * 128 + tid] = nib;
    __syncthreads();

    int txL = xlen[b], tyL = ylen[b];
    if (tid == 0) {
        int idx = txL - 1;
        int y = tyL - 1;
        unsigned wcur = sd[(((y - 1) >= 0 ? (y - 1) : 0) >> 3) * 128 + (idx >> 2)];
        for (; y >= 0; --y) {
            sxs[y] = idx;
            int mv = 0;
            if (idx > 0) {
                if (idx == y) mv = 1;
                else mv = (wcur >> (((y - 1) & 7) * 4 + (idx & 3))) & 1;
            }
            idx -= mv;
            int yn = (y - 2) >= 0 ? (y - 2) : 0;
            wcur = sd[(yn >> 3) * 128 + (idx >> 2)];                 // prefetch next step's word
        }
    }
    __syncthreads();
    // publish xs
    for (int y = tid; y < tyL; y += 128) g_xs[b * TY + y] = sxs[y];
    for (int y = tyL + tid; y < TY; y += 128) g_xs[b * TY + y] = -1;
    // durations via binary search over monotone sxs[0..tyL)
#pragma unroll
    for (int h = 0; h < 4; ++h) {
        int x = h * 128 + tid;
        float dv = 0.0f;
        if (x < txL) {
            int lo = 0, hi = tyL;
            while (lo < hi) { int mid = (lo + hi) >> 1; if (sxs[mid] < x) lo = mid + 1; else hi = mid; }
            int start = lo;
            hi = tyL;
            while (lo < hi) { int mid = (lo + hi) >> 1; if (sxs[mid] < x + 1) lo = mid + 1; else hi = mid; }
            dv = log1pf((float)(lo - start));
        }
        out[OFF_DUR + b * TX + x] = dv;
    }
}

// ---------------- kernel 5: gathers + attn ones ----------------
__global__ void __launch_bounds__(256) gather_kernel(float* __restrict__ out) {
    int t = blockIdx.x * 256 + threadIdx.x;
    if (t >= BB * TY * 20) return;
    int bs = t / 20;
    int c4 = (t % 20) * 4;
    int b  = bs >> 11;
    int xs = g_xs[bs];
    float4 m = make_float4(0.f, 0.f, 0.f, 0.f), l = m;
    if (xs >= 0) {
        size_t rb = ((size_t)b * TX + xs) * CC + c4;
        m = *(const float4*)&g_omT[rb];
        l = *(const float4*)&g_olsT[rb];
        if (c4 == 0) out[OFF_AT + (size_t)bs * TX + xs] = 1.0f;
    }
    *(float4*)&out[OFF_M + (size_t)bs * CC + c4] = m;
    *(float4*)&out[OFF_L + (size_t)bs * CC + c4] = l;
}

// ---------------- launch ----------------
extern "C" void kernel_launch(void* const* d_in, const int* in_sizes, int n_in,
                              void* d_out, int out_size) {
    const float* om   = (const float*)d_in[0];
    const float* ols  = (const float*)d_in[1];
    const float* z    = (const float*)d_in[2];
    const int*   xlen = (const int*)d_in[3];
    const int*   ylen = (const int*)d_in[4];
    float* out = (float*)d_out;

    static bool attr_set = false;
    if (!attr_set) {
        cudaFuncSetAttribute(fwd_kernel, cudaFuncAttributeMaxDynamicSharedMemorySize, FWD_SMEM);
        cudaFuncSetAttribute(gemm_logp, cudaFuncAttributeMaxDynamicSharedMemorySize, GEMM_SMEM);
        attr_set = true;
    }

    prep_kernel<<<dim3(TX / 128, BB), 128>>>(om, ols);
    pre_out<<<496, 512>>>(z, om, ols, ylen, out);
    gemm_logp<<<dim3(TX / 128, TY / 128, BB), 256, GEMM_SMEM>>>(z, xlen, ylen);
    fwd_kernel<<<BB, DPW * 32, FWD_SMEM>>>(xlen, ylen, out);
    gather_kernel<<<(BB * TY * 20 + 255) / 256, 256>>>(out);
}